// round 8
// baseline (speedup 1.0000x reference)
#include <cuda_runtime.h>
#include <math.h>

#define HH 1024
#define WW 1024
#define NPIX (HH * WW)
#define N_ITERS 100

// ---------------- device scratch (statically allocated, ~36 MB) ----------------
__device__ uint4  g_wq[NPIX];       // 8x unorm16 weights per pixel (16B)
__device__ float  g_Y[NPIX];        // luminance plane
__device__ unsigned char g_mask[NPIX];
__device__ float2 g_x0[NPIX];       // ping
__device__ float2 g_x1[NPIX];       // pong

// ---------------- setup ----------------
__global__ void setup_kernel(const float* __restrict__ gray,
                             const float* __restrict__ app) {
    int pix = blockIdx.x * blockDim.x + threadIdx.x;
    if (pix >= NPIX) return;
    float g0 = gray[3*pix+0], g1 = gray[3*pix+1], g2 = gray[3*pix+2];
    float a0 = app [3*pix+0], a1 = app [3*pix+1], a2 = app [3*pix+2];

    const float inv255 = 1.0f / 255.0f;
    float diff = (fabsf(g0-a0) + fabsf(g1-a1) + fabsf(g2-a2)) * inv255;
    bool colored = diff > 0.01f;

    float Y = (0.3f*g0 + 0.59f*g1 + 0.11f*g2) * inv255;

    float ya = (0.3f*a0 + 0.59f*a1 + 0.11f*a2) * inv255;
    float r  = a0 * inv255;
    float bl = a2 * inv255;
    float I = 0.74f*(r - ya) - 0.27f*(bl - ya);
    float Q = 0.48f*(r - ya) + 0.41f*(bl - ya);

    g_Y[pix]    = Y;
    g_x0[pix]   = colored ? make_float2(I, Q) : make_float2(0.0f, 0.0f);
    g_mask[pix] = colored ? 1 : 0;
}

// ---------------- weights: quantized unorm16 ----------------
__global__ void weights_kernel() {
    int pix = blockIdx.x * blockDim.x + threadIdx.x;
    if (pix >= NPIX) return;
    int i = pix / WW, j = pix % WW;

    const int di[8] = {-1,-1,-1, 0, 0, 1, 1, 1};
    const int dj[8] = {-1, 0, 1,-1, 1,-1, 0, 1};

    float Y = g_Y[pix];
    float nbr[8], valid[8];
    #pragma unroll
    for (int k = 0; k < 8; k++) {
        int ii = i + di[k], jj = j + dj[k];
        bool in = (ii >= 0) & (ii < HH) & (jj >= 0) & (jj < WW);
        valid[k] = in ? 1.0f : 0.0f;
        nbr[k]   = in ? g_Y[ii*WW + jj] : 0.0f;
    }

    float count = 1.0f, s = Y;
    #pragma unroll
    for (int k = 0; k < 8; k++) { count += valid[k]; s += nbr[k] * valid[k]; }
    float mean = s / count;

    float var = (Y - mean) * (Y - mean);
    #pragma unroll
    for (int k = 0; k < 8; k++) {
        float d = nbr[k] - mean;
        var += d * d * valid[k];
    }
    var /= count;
    float vs = fmaxf(0.6f * var, 2e-6f);
    float inv_vs = 1.0f / vs;

    float w[8], wsum = 0.0f;
    #pragma unroll
    for (int k = 0; k < 8; k++) {
        float d = nbr[k] - Y;
        w[k] = expf(-d * d * inv_vs) * valid[k];
        wsum += w[k];
    }
    // colored pixels: all weights 0 (the all-zero pattern encodes "colored")
    float scale = (g_mask[pix] ? 0.0f : 1.0f) / wsum * 65535.0f;

    unsigned int u[8];
    #pragma unroll
    for (int k = 0; k < 8; k++) u[k] = (unsigned int)rintf(w[k] * scale);

    uint4 q;
    q.x = u[0] | (u[1] << 16);
    q.y = u[2] | (u[3] << 16);
    q.z = u[4] | (u[5] << 16);
    q.w = u[6] | (u[7] << 16);
    g_wq[pix] = q;
}

// unpack helper: 8 weights + colored flag from uint4
__device__ __forceinline__ void unpack_w(uint4 q, float* w, float& c) {
    const float S = 1.0f / 65535.0f;
    w[0] = (float)(q.x & 0xFFFFu) * S;  w[1] = (float)(q.x >> 16) * S;
    w[2] = (float)(q.y & 0xFFFFu) * S;  w[3] = (float)(q.y >> 16) * S;
    w[4] = (float)(q.z & 0xFFFFu) * S;  w[5] = (float)(q.z >> 16) * S;
    w[6] = (float)(q.w & 0xFFFFu) * S;  w[7] = (float)(q.w >> 16) * S;
    c = ((q.x | q.y | q.z | q.w) == 0u) ? 1.0f : 0.0f;
}

// ---------------- main stencil iteration: 2 pixels/thread, float4 loads ----------
// Thread handles columns (j0, j0+1), j0 even. Each row's 6 needed float2 values
// (cols j0-2..j0+3, superset of j0-1..j0+2) arrive as 3 float4 loads.
// Border columns: clamped load index puts a garbage value in the slot, but that
// slot's weight is exactly 0.
__global__ void __launch_bounds__(256)
iter_kernel(int src_is_x0) {
    int tx = threadIdx.x;                       // 0..31
    int j0 = (blockIdx.x * 32 + tx) * 2;        // even column
    int i  = blockIdx.y * 8 + threadIdx.y;
    int pix = i * WW + j0;

    const float2* __restrict__ xin  = src_is_x0 ? g_x0 : g_x1;
    float2*       __restrict__ xout = src_is_x0 ? g_x1 : g_x0;

    int im = (i > 0)      ? i - 1 : 0;
    int ip = (i < HH - 1) ? i + 1 : HH - 1;

    int eL = max(j0 - 2, 0) >> 1;               // float4 index of cols (j0-2, j0-1)
    int eC = j0 >> 1;                           //                     (j0,   j0+1)
    int eR = min(j0 + 2, WW - 2) >> 1;          //                     (j0+2, j0+3)

    const float4* rm4 = (const float4*)(xin + im * WW);
    const float4* r04 = (const float4*)(xin + i  * WW);
    const float4* rp4 = (const float4*)(xin + ip * WW);

    float4 Am = rm4[eL], Bm = rm4[eC], Cm = rm4[eR];
    float4 A0 = r04[eL], B0 = r04[eC], C0 = r04[eR];
    float4 Ap = rp4[eL], Bp = rp4[eC], Cp = rp4[eR];

    uint4 qa = g_wq[pix];
    uint4 qb = g_wq[pix + 1];
    float wa[8], wb[8], ca, cb;
    unpack_w(qa, wa, ca);
    unpack_w(qb, wb, cb);

    // ---- pixel 0 (col j0): L=*.zw of A-col, C=B.xy, R=B.zw ----
    float ax = ca * B0.x, ay = ca * B0.y;
    ax = fmaf(wa[0], Am.z, ax); ay = fmaf(wa[0], Am.w, ay);   // (-1,-1)
    ax = fmaf(wa[1], Bm.x, ax); ay = fmaf(wa[1], Bm.y, ay);   // (-1, 0)
    ax = fmaf(wa[2], Bm.z, ax); ay = fmaf(wa[2], Bm.w, ay);   // (-1,+1)
    ax = fmaf(wa[3], A0.z, ax); ay = fmaf(wa[3], A0.w, ay);   // ( 0,-1)
    ax = fmaf(wa[4], B0.z, ax); ay = fmaf(wa[4], B0.w, ay);   // ( 0,+1)
    ax = fmaf(wa[5], Ap.z, ax); ay = fmaf(wa[5], Ap.w, ay);   // (+1,-1)
    ax = fmaf(wa[6], Bp.x, ax); ay = fmaf(wa[6], Bp.y, ay);   // (+1, 0)
    ax = fmaf(wa[7], Bp.z, ax); ay = fmaf(wa[7], Bp.w, ay);   // (+1,+1)

    // ---- pixel 1 (col j0+1): L=B.xy, C=B.zw, R=C.xy ----
    float bx = cb * B0.z, by = cb * B0.w;
    bx = fmaf(wb[0], Bm.x, bx); by = fmaf(wb[0], Bm.y, by);
    bx = fmaf(wb[1], Bm.z, bx); by = fmaf(wb[1], Bm.w, by);
    bx = fmaf(wb[2], Cm.x, bx); by = fmaf(wb[2], Cm.y, by);
    bx = fmaf(wb[3], B0.x, bx); by = fmaf(wb[3], B0.y, by);
    bx = fmaf(wb[4], C0.x, bx); by = fmaf(wb[4], C0.y, by);
    bx = fmaf(wb[5], Bp.x, bx); by = fmaf(wb[5], Bp.y, by);
    bx = fmaf(wb[6], Bp.z, bx); by = fmaf(wb[6], Bp.w, by);
    bx = fmaf(wb[7], Cp.x, bx); by = fmaf(wb[7], Cp.y, by);

    float4 outv = make_float4(ax, ay, bx, by);
    *(float4*)(xout + pix) = outv;
}

// ---------------- fused last step + YIQ->RGB ----------------
__global__ void __launch_bounds__(256)
iter_final_kernel(float* __restrict__ out, int src_is_x0) {
    int tx = threadIdx.x;
    int j0 = (blockIdx.x * 32 + tx) * 2;
    int i  = blockIdx.y * 8 + threadIdx.y;
    int pix = i * WW + j0;

    const float2* __restrict__ xin = src_is_x0 ? g_x0 : g_x1;

    int im = (i > 0)      ? i - 1 : 0;
    int ip = (i < HH - 1) ? i + 1 : HH - 1;
    int eL = max(j0 - 2, 0) >> 1;
    int eC = j0 >> 1;
    int eR = min(j0 + 2, WW - 2) >> 1;

    const float4* rm4 = (const float4*)(xin + im * WW);
    const float4* r04 = (const float4*)(xin + i  * WW);
    const float4* rp4 = (const float4*)(xin + ip * WW);

    float4 Am = rm4[eL], Bm = rm4[eC], Cm = rm4[eR];
    float4 A0 = r04[eL], B0 = r04[eC], C0 = r04[eR];
    float4 Ap = rp4[eL], Bp = rp4[eC], Cp = rp4[eR];

    uint4 qa = g_wq[pix];
    uint4 qb = g_wq[pix + 1];
    float wa[8], wb[8], ca, cb;
    unpack_w(qa, wa, ca);
    unpack_w(qb, wb, cb);

    float ax = ca * B0.x, ay = ca * B0.y;
    ax = fmaf(wa[0], Am.z, ax); ay = fmaf(wa[0], Am.w, ay);
    ax = fmaf(wa[1], Bm.x, ax); ay = fmaf(wa[1], Bm.y, ay);
    ax = fmaf(wa[2], Bm.z, ax); ay = fmaf(wa[2], Bm.w, ay);
    ax = fmaf(wa[3], A0.z, ax); ay = fmaf(wa[3], A0.w, ay);
    ax = fmaf(wa[4], B0.z, ax); ay = fmaf(wa[4], B0.w, ay);
    ax = fmaf(wa[5], Ap.z, ax); ay = fmaf(wa[5], Ap.w, ay);
    ax = fmaf(wa[6], Bp.x, ax); ay = fmaf(wa[6], Bp.y, ay);
    ax = fmaf(wa[7], Bp.z, ax); ay = fmaf(wa[7], Bp.w, ay);

    float bx = cb * B0.z, by = cb * B0.w;
    bx = fmaf(wb[0], Bm.x, bx); by = fmaf(wb[0], Bm.y, by);
    bx = fmaf(wb[1], Bm.z, bx); by = fmaf(wb[1], Bm.w, by);
    bx = fmaf(wb[2], Cm.x, bx); by = fmaf(wb[2], Cm.y, by);
    bx = fmaf(wb[3], B0.x, bx); by = fmaf(wb[3], B0.y, by);
    bx = fmaf(wb[4], C0.x, bx); by = fmaf(wb[4], C0.y, by);
    bx = fmaf(wb[5], Bp.x, bx); by = fmaf(wb[5], Bp.y, by);
    bx = fmaf(wb[6], Bp.z, bx); by = fmaf(wb[6], Bp.w, by);
    bx = fmaf(wb[7], Cp.x, bx); by = fmaf(wb[7], Cp.y, by);

    // YIQ -> RGB for both pixels
    #pragma unroll
    for (int p = 0; p < 2; p++) {
        float I = p ? bx : ax;
        float Q = p ? by : ay;
        float y = g_Y[pix + p];
        float r = y + 0.9468822170900693f  * I + 0.6235565819861433f * Q;
        float g = y - 0.27478764629897834f * I - 0.6356910791873801f * Q;
        float b = y - 1.1085450346420322f  * I + 1.7090069284064666f * Q;
        int o = 3 * (pix + p);
        out[o+0] = fminf(fmaxf(r, 0.0f), 1.0f) * 255.0f;
        out[o+1] = fminf(fmaxf(g, 0.0f), 1.0f) * 255.0f;
        out[o+2] = fminf(fmaxf(b, 0.0f), 1.0f) * 255.0f;
    }
}

extern "C" void kernel_launch(void* const* d_in, const int* in_sizes, int n_in,
                              void* d_out, int out_size) {
    const float* gray = (const float*)d_in[0];
    const float* app  = (const float*)d_in[1];
    float* out = (float*)d_out;

    int threads = 256;
    int blocks1d = (NPIX + threads - 1) / threads;

    setup_kernel<<<blocks1d, threads>>>(gray, app);
    weights_kernel<<<blocks1d, threads>>>();

    dim3 blk(32, 8);
    dim3 grd(WW / 64, HH / 8);   // 16 x 128 = 2048 blocks, 2 px/thread
    int src_is_x0 = 1;
    for (int it = 0; it < N_ITERS - 1; it++) {   // 99 normal steps
        iter_kernel<<<grd, blk>>>(src_is_x0);
        src_is_x0 ^= 1;
    }
    // step 100 fused with YIQ->RGB (after 99 steps, src_is_x0 == 0: field in g_x1)
    iter_final_kernel<<<grd, blk>>>(out, src_is_x0);
}